// round 3
// baseline (speedup 1.0000x reference)
#include <cuda_runtime.h>

// ---------------- problem constants ----------------
#define BB    16
#define NPTS  4096
#define MPTS  1024
#define C1CH  128
#define C2CH  256
#define KIN   384          // C1 + C2
#define OC    256          // MLP0 == MLP1 == 256
#define ROWS  (BB * NPTS)  // 65536
#define EPSBN 1e-5f

// ---------------- device scratch (static, allocation-free) ----------------
__device__ float g_p2t[BB * MPTS * C2CH];     // points2 transposed (B, M, C2)
__device__ float g_feat[ROWS * KIN];          // concat features (row-major, 384)
__device__ int   g_idx[ROWS * 3];
__device__ float g_wgt[ROWS * 3];
__device__ float g_h1[ROWS * OC];             // GEMM1 raw output
__device__ float g_h2[ROWS * OC];             // GEMM2 raw output
__device__ float g_ps1[256 * OC], g_pq1[256 * OC];   // BN1 partial sums / sumsq
__device__ float g_ps2[256 * OC], g_pq2[256 * OC];   // BN2 partial sums / sumsq
__device__ float g_scale1[OC], g_bias1[OC];
__device__ float g_scale2[OC], g_bias2[OC];

// ---------------- transpose points2: (B, C2, M) -> (B, M, C2) ----------------
__global__ void k_transpose_p2(const float* __restrict__ p2) {
    __shared__ float tile[32][33];
    const int b  = blockIdx.z;
    const int m0 = blockIdx.x * 32, c0 = blockIdx.y * 32;
    const int tx = threadIdx.x, ty = threadIdx.y;
    const float* in = p2 + (size_t)b * C2CH * MPTS;
#pragma unroll
    for (int i = 0; i < 4; i++)
        tile[ty + i * 8][tx] = in[(size_t)(c0 + ty + i * 8) * MPTS + m0 + tx];
    __syncthreads();
    float* out = g_p2t + (size_t)b * MPTS * C2CH;
#pragma unroll
    for (int i = 0; i < 4; i++)
        out[(size_t)(m0 + ty + i * 8) * C2CH + c0 + tx] = tile[tx][ty + i * 8];
}

// ---------------- transpose points1 into feat cols [256..384) ----------------
__global__ void k_transpose_p1(const float* __restrict__ p1) {
    __shared__ float tile[32][33];
    const int b  = blockIdx.z;
    const int n0 = blockIdx.x * 32, c0 = blockIdx.y * 32;
    const int tx = threadIdx.x, ty = threadIdx.y;
    const float* in = p1 + (size_t)b * C1CH * NPTS;
#pragma unroll
    for (int i = 0; i < 4; i++)
        tile[ty + i * 8][tx] = in[(size_t)(c0 + ty + i * 8) * NPTS + n0 + tx];
    __syncthreads();
#pragma unroll
    for (int i = 0; i < 4; i++) {
        const int n = n0 + ty + i * 8;
        g_feat[(size_t)(b * NPTS + n) * KIN + C2CH + c0 + tx] = tile[tx][ty + i * 8];
    }
}

// ---------------- 3-NN over M=1024 (xyz2 staged in SMEM) ----------------
__global__ void k_knn(const float* __restrict__ xyz1, const float* __restrict__ xyz2) {
    __shared__ float4 s2[MPTS];
    const int b   = blockIdx.y;
    const int tid = threadIdx.x;
    const float* x2 = xyz2 + (size_t)b * 3 * MPTS;
    for (int m = tid; m < MPTS; m += 256)
        s2[m] = make_float4(x2[m], x2[m + MPTS], x2[m + 2 * MPTS], 0.f);
    __syncthreads();

    const int n = blockIdx.x * 256 + tid;
    const float* x1 = xyz1 + (size_t)b * 3 * NPTS;
    const float px = x1[n], py = x1[n + NPTS], pz = x1[n + 2 * NPTS];

    float d0 = 3.4e38f, d1 = 3.4e38f, d2 = 3.4e38f;
    int   i0 = 0, i1 = 0, i2 = 0;
#pragma unroll 4
    for (int m = 0; m < MPTS; m++) {
        const float4 q = s2[m];
        const float dx = px - q.x, dy = py - q.y, dz = pz - q.z;
        const float d = fmaf(dx, dx, fmaf(dy, dy, dz * dz));
        if (d < d2) {
            if (d < d1) {
                d2 = d1; i2 = i1;
                if (d < d0) { d1 = d0; i1 = i0; d0 = d; i0 = m; }
                else        { d1 = d;  i1 = m; }
            } else { d2 = d; i2 = m; }
        }
    }
    d0 = fmaxf(d0, 1e-10f); d1 = fmaxf(d1, 1e-10f); d2 = fmaxf(d2, 1e-10f);
    const float w0 = 1.f / d0, w1 = 1.f / d1, w2 = 1.f / d2;
    const float inv = 1.f / (w0 + w1 + w2);
    const int row = b * NPTS + n;
    g_idx[row * 3 + 0] = i0; g_idx[row * 3 + 1] = i1; g_idx[row * 3 + 2] = i2;
    g_wgt[row * 3 + 0] = w0 * inv; g_wgt[row * 3 + 1] = w1 * inv; g_wgt[row * 3 + 2] = w2 * inv;
}

// ---------------- weighted gather -> feat cols [0..256) (warp per row) ----------------
__global__ void k_interp() {
    const int tid  = threadIdx.x;
    const int warp = tid >> 5, lane = tid & 31;
    const int row  = blockIdx.x * 4 + warp;
    const int b    = row >> 12;   // / NPTS
    const int i0 = g_idx[row * 3 + 0], i1 = g_idx[row * 3 + 1], i2 = g_idx[row * 3 + 2];
    const float w0 = g_wgt[row * 3 + 0], w1 = g_wgt[row * 3 + 1], w2 = g_wgt[row * 3 + 2];
    const float4* f0 = (const float4*)(g_p2t + ((size_t)b * MPTS + i0) * C2CH);
    const float4* f1 = (const float4*)(g_p2t + ((size_t)b * MPTS + i1) * C2CH);
    const float4* f2 = (const float4*)(g_p2t + ((size_t)b * MPTS + i2) * C2CH);
    float4* dst = (float4*)(g_feat + (size_t)row * KIN);
#pragma unroll
    for (int j = lane; j < C2CH / 4; j += 32) {
        const float4 a = f0[j], c = f1[j], e = f2[j];
        float4 r;
        r.x = fmaf(w0, a.x, fmaf(w1, c.x, w2 * e.x));
        r.y = fmaf(w0, a.y, fmaf(w1, c.y, w2 * e.y));
        r.z = fmaf(w0, a.z, fmaf(w1, c.z, w2 * e.z));
        r.w = fmaf(w0, a.w, fmaf(w1, c.w, w2 * e.w));
        dst[j] = r;
    }
}

// ---------------- 128x128x8 double-buffered SGEMM: C = A(ROWSxK) * W(OCxK)^T ----
// BNR: apply y = relu(a*scale[k] + bias[k]) to A elements on load (fused BN1+ReLU).
template <int KDIM, bool BNR>
__device__ __forceinline__ void sgemm_body(const float* __restrict__ A,
                                           const float* __restrict__ W,
                                           float* __restrict__ C,
                                           const float* __restrict__ scale,
                                           const float* __restrict__ bias) {
    __shared__ float As[2][8][128];
    __shared__ float Bs[2][8][128];
    __shared__ float ssc[BNR ? KDIM : 1];
    __shared__ float sbi[BNR ? KDIM : 1];

    const int tid  = threadIdx.x;
    const int row0 = blockIdx.y * 128, col0 = blockIdx.x * 128;
    const int lrow = tid >> 1;          // 0..127
    const int k4   = (tid & 1) * 4;     // 0 or 4
    const int tx   = tid & 15, ty = tid >> 4;

    if (BNR) {
        for (int i = tid; i < KDIM; i += 256) { ssc[i] = scale[i]; sbi[i] = bias[i]; }
        __syncthreads();
    }

    const float* Ap = A + (size_t)(row0 + lrow) * KDIM + k4;
    const float* Wp = W + (size_t)(col0 + lrow) * KDIM + k4;

    float acc[8][8];
#pragma unroll
    for (int i = 0; i < 8; i++)
#pragma unroll
        for (int j = 0; j < 8; j++) acc[i][j] = 0.f;

    // prologue: tile 0
    float4 a4 = *(const float4*)Ap;
    float4 w4 = *(const float4*)Wp;
    if (BNR) {
        a4.x = fmaxf(fmaf(a4.x, ssc[k4 + 0], sbi[k4 + 0]), 0.f);
        a4.y = fmaxf(fmaf(a4.y, ssc[k4 + 1], sbi[k4 + 1]), 0.f);
        a4.z = fmaxf(fmaf(a4.z, ssc[k4 + 2], sbi[k4 + 2]), 0.f);
        a4.w = fmaxf(fmaf(a4.w, ssc[k4 + 3], sbi[k4 + 3]), 0.f);
    }
    As[0][k4 + 0][lrow] = a4.x; As[0][k4 + 1][lrow] = a4.y;
    As[0][k4 + 2][lrow] = a4.z; As[0][k4 + 3][lrow] = a4.w;
    Bs[0][k4 + 0][lrow] = w4.x; Bs[0][k4 + 1][lrow] = w4.y;
    Bs[0][k4 + 2][lrow] = w4.z; Bs[0][k4 + 3][lrow] = w4.w;
    __syncthreads();

    const int NT = KDIM / 8;
    int buf = 0;
    for (int t = 0; t < NT; t++) {
        float4 na, nw;
        if (t + 1 < NT) {
            na = *(const float4*)(Ap + (t + 1) * 8);
            nw = *(const float4*)(Wp + (t + 1) * 8);
        }
#pragma unroll
        for (int kk = 0; kk < 8; kk++) {
            float af[8], bf[8];
            *(float4*)(af)     = *(const float4*)&As[buf][kk][ty * 8];
            *(float4*)(af + 4) = *(const float4*)&As[buf][kk][ty * 8 + 4];
            *(float4*)(bf)     = *(const float4*)&Bs[buf][kk][tx * 8];
            *(float4*)(bf + 4) = *(const float4*)&Bs[buf][kk][tx * 8 + 4];
#pragma unroll
            for (int i = 0; i < 8; i++)
#pragma unroll
                for (int j = 0; j < 8; j++)
                    acc[i][j] = fmaf(af[i], bf[j], acc[i][j]);
        }
        if (t + 1 < NT) {
            if (BNR) {
                const int kb = (t + 1) * 8 + k4;
                na.x = fmaxf(fmaf(na.x, ssc[kb + 0], sbi[kb + 0]), 0.f);
                na.y = fmaxf(fmaf(na.y, ssc[kb + 1], sbi[kb + 1]), 0.f);
                na.z = fmaxf(fmaf(na.z, ssc[kb + 2], sbi[kb + 2]), 0.f);
                na.w = fmaxf(fmaf(na.w, ssc[kb + 3], sbi[kb + 3]), 0.f);
            }
            buf ^= 1;
            As[buf][k4 + 0][lrow] = na.x; As[buf][k4 + 1][lrow] = na.y;
            As[buf][k4 + 2][lrow] = na.z; As[buf][k4 + 3][lrow] = na.w;
            Bs[buf][k4 + 0][lrow] = nw.x; Bs[buf][k4 + 1][lrow] = nw.y;
            Bs[buf][k4 + 2][lrow] = nw.z; Bs[buf][k4 + 3][lrow] = nw.w;
            __syncthreads();
        }
    }

#pragma unroll
    for (int i = 0; i < 8; i++) {
        const size_t r = (size_t)(row0 + ty * 8 + i) * OC + col0 + tx * 8;
        *(float4*)&C[r]     = make_float4(acc[i][0], acc[i][1], acc[i][2], acc[i][3]);
        *(float4*)&C[r + 4] = make_float4(acc[i][4], acc[i][5], acc[i][6], acc[i][7]);
    }
}

__global__ __launch_bounds__(256) void k_gemm1(const float* __restrict__ W1) {
    sgemm_body<KIN, false>(g_feat, W1, g_h1, nullptr, nullptr);
}
__global__ __launch_bounds__(256) void k_gemm2(const float* __restrict__ W2) {
    sgemm_body<OC, true>(g_h1, W2, g_h2, g_scale1, g_bias1);
}

// ---------------- BN stats: deterministic two-pass partial reduction ----------------
__device__ __forceinline__ void stats_body(const float* __restrict__ h,
                                           float* __restrict__ psum,
                                           float* __restrict__ psq) {
    const int c = threadIdx.x;            // channel
    const size_t r0 = (size_t)blockIdx.x * 256;
    const float* p = h + r0 * OC + c;
    float s = 0.f, q = 0.f;
#pragma unroll 4
    for (int i = 0; i < 256; i++) {
        const float v = p[(size_t)i * OC];
        s += v;
        q = fmaf(v, v, q);
    }
    psum[blockIdx.x * OC + c] = s;
    psq[blockIdx.x * OC + c]  = q;
}
__global__ void k_stats1() { stats_body(g_h1, g_ps1, g_pq1); }
__global__ void k_stats2() { stats_body(g_h2, g_ps2, g_pq2); }

__device__ __forceinline__ void fin_body(const float* __restrict__ psum,
                                         const float* __restrict__ psq,
                                         const float* __restrict__ gamma,
                                         const float* __restrict__ beta,
                                         float* __restrict__ scale,
                                         float* __restrict__ bias) {
    const int c = threadIdx.x;
    float s = 0.f, q = 0.f;
    for (int i = 0; i < 256; i++) { s += psum[i * OC + c]; q += psq[i * OC + c]; }
    const float invN = 1.f / (float)ROWS;
    const float mean = s * invN;
    const float var  = q * invN - mean * mean;
    const float sc   = gamma[c] * rsqrtf(var + EPSBN);
    scale[c] = sc;
    bias[c]  = fmaf(-mean, sc, beta[c]);
}
__global__ void k_fin1(const float* __restrict__ g, const float* __restrict__ b) {
    fin_body(g_ps1, g_pq1, g, b, g_scale1, g_bias1);
}
__global__ void k_fin2(const float* __restrict__ g, const float* __restrict__ b) {
    fin_body(g_ps2, g_pq2, g, b, g_scale2, g_bias2);
}

// ---------------- BN2+ReLU + transpose to (B, 256, N) ----------------
__global__ void k_out(float* __restrict__ out) {
    __shared__ float tile[32][33];
    const int b  = blockIdx.z;
    const int n0 = blockIdx.x * 32, c0 = blockIdx.y * 32;
    const int tx = threadIdx.x, ty = threadIdx.y;
#pragma unroll
    for (int i = 0; i < 4; i++) {
        const int n = n0 + ty + i * 8, c = c0 + tx;
        const float v = g_h2[(size_t)(b * NPTS + n) * OC + c];
        tile[ty + i * 8][tx] = fmaxf(fmaf(v, g_scale2[c], g_bias2[c]), 0.f);
    }
    __syncthreads();
    float* o = out + (size_t)b * OC * NPTS;
#pragma unroll
    for (int i = 0; i < 4; i++)
        o[(size_t)(c0 + ty + i * 8) * NPTS + n0 + tx] = tile[tx][ty + i * 8];
}

// ---------------- launch ----------------
extern "C" void kernel_launch(void* const* d_in, const int* in_sizes, int n_in,
                              void* d_out, int out_size) {
    const float* xyz1    = (const float*)d_in[0];
    const float* xyz2    = (const float*)d_in[1];
    const float* points1 = (const float*)d_in[2];
    const float* points2 = (const float*)d_in[3];
    const float* W1      = (const float*)d_in[4];
    const float* gamma1  = (const float*)d_in[5];
    const float* beta1   = (const float*)d_in[6];
    const float* W2      = (const float*)d_in[7];
    const float* gamma2  = (const float*)d_in[8];
    const float* beta2   = (const float*)d_in[9];
    float* out = (float*)d_out;

    k_transpose_p2<<<dim3(MPTS / 32, C2CH / 32, BB), dim3(32, 8)>>>(points2);
    k_knn<<<dim3(NPTS / 256, BB), 256>>>(xyz1, xyz2);
    k_interp<<<ROWS / 4, 128>>>();
    k_transpose_p1<<<dim3(NPTS / 32, C1CH / 32, BB), dim3(32, 8)>>>(points1);

    k_gemm1<<<dim3(OC / 128, ROWS / 128), 256>>>(W1);
    k_stats1<<<256, 256>>>();
    k_fin1<<<1, 256>>>(gamma1, beta1);

    k_gemm2<<<dim3(OC / 128, ROWS / 128), 256>>>(W2);
    k_stats2<<<256, 256>>>();
    k_fin2<<<1, 256>>>(gamma2, beta2);

    k_out<<<dim3(NPTS / 32, OC / 32, BB), dim3(32, 8)>>>(out);
}

// round 10
// speedup vs baseline: 2.0816x; 2.0816x over previous
#include <cuda_runtime.h>
#include <cuda_bf16.h>
#include <cstdint>

// ---------------- problem constants ----------------
#define BB    16
#define NPTS  4096
#define MPTS  1024
#define C1CH  128
#define C2CH  256
#define KIN   384          // C1 + C2
#define OC    256          // MLP0 == MLP1 == 256
#define ROWS  (BB * NPTS)  // 65536
#define EPSBN 1e-5f

// ---------------- device scratch (static, allocation-free, 16B aligned) ----------------
__device__ __align__(16) float g_p2t[BB * MPTS * C2CH];
__device__ __align__(16) __nv_bfloat16 g_featH[ROWS * KIN];
__device__ __align__(16) __nv_bfloat16 g_featL[ROWS * KIN];
__device__ __align__(16) int   g_idx[ROWS * 3];
__device__ __align__(16) float g_wgt[ROWS * 3];
__device__ __align__(16) float g_h1[ROWS * OC];
__device__ __align__(16) __nv_bfloat16 g_h1H[ROWS * OC];
__device__ __align__(16) __nv_bfloat16 g_h1L[ROWS * OC];
__device__ __align__(16) float g_h2[ROWS * OC];
__device__ __align__(16) __nv_bfloat16 g_w1h[OC * KIN], g_w1l[OC * KIN];
__device__ __align__(16) __nv_bfloat16 g_w2h[OC * OC],  g_w2l[OC * OC];
__device__ __align__(16) float g_ps1[256 * OC], g_pq1[256 * OC];
__device__ __align__(16) float g_ps2[256 * OC], g_pq2[256 * OC];
__device__ __align__(16) float g_scale1[OC], g_bias1[OC];
__device__ __align__(16) float g_scale2[OC], g_bias2[OC];

// ---------------- helpers ----------------
__device__ __forceinline__ void mma16816(float* d, const uint32_t* a, const uint32_t* b) {
    asm volatile("mma.sync.aligned.m16n8k16.row.col.f32.bf16.bf16.f32 "
        "{%0,%1,%2,%3}, {%4,%5,%6,%7}, {%8,%9}, {%0,%1,%2,%3};"
        : "+f"(d[0]), "+f"(d[1]), "+f"(d[2]), "+f"(d[3])
        : "r"(a[0]), "r"(a[1]), "r"(a[2]), "r"(a[3]), "r"(b[0]), "r"(b[1]));
}

__device__ __forceinline__ void split_bf16(float v, __nv_bfloat16& h, __nv_bfloat16& l) {
    h = __float2bfloat16(v);
    l = __float2bfloat16(v - __bfloat162float(h));
}

// ---------------- transpose points2: (B, C2, M) -> (B, M, C2) ----------------
__global__ void k_transpose_p2(const float* __restrict__ p2) {
    __shared__ float tile[32][33];
    const int b  = blockIdx.z;
    const int m0 = blockIdx.x * 32, c0 = blockIdx.y * 32;
    const int tx = threadIdx.x, ty = threadIdx.y;
    const float* in = p2 + (size_t)b * C2CH * MPTS;
#pragma unroll
    for (int i = 0; i < 4; i++)
        tile[ty + i * 8][tx] = in[(size_t)(c0 + ty + i * 8) * MPTS + m0 + tx];
    __syncthreads();
    float* out = g_p2t + (size_t)b * MPTS * C2CH;
#pragma unroll
    for (int i = 0; i < 4; i++)
        out[(size_t)(m0 + ty + i * 8) * C2CH + c0 + tx] = tile[tx][ty + i * 8];
}

// ---------------- transpose points1 -> split-bf16 feat cols [256..384) ----------------
__global__ void k_transpose_p1(const float* __restrict__ p1) {
    __shared__ float tile[32][33];
    const int b  = blockIdx.z;
    const int n0 = blockIdx.x * 32, c0 = blockIdx.y * 32;
    const int tx = threadIdx.x, ty = threadIdx.y;
    const float* in = p1 + (size_t)b * C1CH * NPTS;
#pragma unroll
    for (int i = 0; i < 4; i++)
        tile[ty + i * 8][tx] = in[(size_t)(c0 + ty + i * 8) * NPTS + n0 + tx];
    __syncthreads();
#pragma unroll
    for (int i = 0; i < 4; i++) {
        const int n = n0 + ty + i * 8;
        const size_t o = (size_t)(b * NPTS + n) * KIN + C2CH + c0 + tx;
        __nv_bfloat16 h, l;
        split_bf16(tile[tx][ty + i * 8], h, l);
        g_featH[o] = h; g_featL[o] = l;
    }
}

// ---------------- 3-NN over M=1024 (xyz2 staged in SMEM) ----------------
__global__ void k_knn(const float* __restrict__ xyz1, const float* __restrict__ xyz2) {
    __shared__ float4 s2[MPTS];
    const int b   = blockIdx.y;
    const int tid = threadIdx.x;
    const float* x2 = xyz2 + (size_t)b * 3 * MPTS;
    for (int m = tid; m < MPTS; m += 256)
        s2[m] = make_float4(x2[m], x2[m + MPTS], x2[m + 2 * MPTS], 0.f);
    __syncthreads();

    const int n = blockIdx.x * 256 + tid;
    const float* x1 = xyz1 + (size_t)b * 3 * NPTS;
    const float px = x1[n], py = x1[n + NPTS], pz = x1[n + 2 * NPTS];

    float d0 = 3.4e38f, d1 = 3.4e38f, d2 = 3.4e38f;
    int   i0 = 0, i1 = 0, i2 = 0;
#pragma unroll 4
    for (int m = 0; m < MPTS; m++) {
        const float4 q = s2[m];
        const float dx = px - q.x, dy = py - q.y, dz = pz - q.z;
        const float d = fmaf(dx, dx, fmaf(dy, dy, dz * dz));
        if (d < d2) {
            if (d < d1) {
                d2 = d1; i2 = i1;
                if (d < d0) { d1 = d0; i1 = i0; d0 = d; i0 = m; }
                else        { d1 = d;  i1 = m; }
            } else { d2 = d; i2 = m; }
        }
    }
    d0 = fmaxf(d0, 1e-10f); d1 = fmaxf(d1, 1e-10f); d2 = fmaxf(d2, 1e-10f);
    const float w0 = 1.f / d0, w1 = 1.f / d1, w2 = 1.f / d2;
    const float inv = 1.f / (w0 + w1 + w2);
    const int row = b * NPTS + n;
    g_idx[row * 3 + 0] = i0; g_idx[row * 3 + 1] = i1; g_idx[row * 3 + 2] = i2;
    g_wgt[row * 3 + 0] = w0 * inv; g_wgt[row * 3 + 1] = w1 * inv; g_wgt[row * 3 + 2] = w2 * inv;
}

// -------- weighted gather -> split-bf16 feat cols [0..256) (warp per row) --------
__global__ void k_interp() {
    const int tid  = threadIdx.x;
    const int warp = tid >> 5, lane = tid & 31;
    const int row  = blockIdx.x * 4 + warp;
    const int b    = row >> 12;
    const int i0 = g_idx[row * 3 + 0], i1 = g_idx[row * 3 + 1], i2 = g_idx[row * 3 + 2];
    const float w0 = g_wgt[row * 3 + 0], w1 = g_wgt[row * 3 + 1], w2 = g_wgt[row * 3 + 2];
    const float4* f0 = (const float4*)(g_p2t + ((size_t)b * MPTS + i0) * C2CH);
    const float4* f1 = (const float4*)(g_p2t + ((size_t)b * MPTS + i1) * C2CH);
    const float4* f2 = (const float4*)(g_p2t + ((size_t)b * MPTS + i2) * C2CH);
    union { __nv_bfloat16 b8[8]; uint4 u; } uh, ul;
#pragma unroll
    for (int half = 0; half < 2; half++) {
        const int j = lane * 2 + half;
        const float4 a = f0[j], c = f1[j], e = f2[j];
        float r[4];
        r[0] = fmaf(w0, a.x, fmaf(w1, c.x, w2 * e.x));
        r[1] = fmaf(w0, a.y, fmaf(w1, c.y, w2 * e.y));
        r[2] = fmaf(w0, a.z, fmaf(w1, c.z, w2 * e.z));
        r[3] = fmaf(w0, a.w, fmaf(w1, c.w, w2 * e.w));
#pragma unroll
        for (int q = 0; q < 4; q++)
            split_bf16(r[q], uh.b8[half * 4 + q], ul.b8[half * 4 + q]);
    }
    const size_t o = (size_t)row * KIN + lane * 8;
    *(uint4*)(g_featH + o) = uh.u;
    *(uint4*)(g_featL + o) = ul.u;
}

// ---------------- weight split prep ----------------
__global__ void k_prep_w(const float* __restrict__ W1, const float* __restrict__ W2) {
    const int i = blockIdx.x * 256 + threadIdx.x;
    if (i < OC * KIN) split_bf16(W1[i], g_w1h[i], g_w1l[i]);
    if (i < OC * OC)  split_bf16(W2[i], g_w2h[i], g_w2l[i]);
}

// ---------------- bf16x3-split GEMM via mma.sync: C = A(ROWSxK) * W(OCxK)^T ----
// CTA 128x128, 8 warps (4m x 2n), warp tile 32x64. Single-buffer SMEM, K=16 stages.
// Fragments via direct LDS.32; 48B-padded rows -> provably conflict-free.
// NOTE: all data pointers are bound INSIDE device code via the __global__ wrappers
// below (passing __device__ symbols from host code was the R5/R8 failure).
template <int KDIM>
__device__ __forceinline__ void gemm_body(
        const __nv_bfloat16* __restrict__ Ah_, const __nv_bfloat16* __restrict__ Al_,
        const __nv_bfloat16* __restrict__ Wh_, const __nv_bfloat16* __restrict__ Wl_,
        float* __restrict__ C) {
    __shared__ __align__(16) __nv_bfloat16 sm[4][128][24];   // Ah | Al | Bh | Bl
    const int tid  = threadIdx.x;
    const int lane = tid & 31, wid = tid >> 5;
    const int warp_m = wid & 3, warp_n = wid >> 2;
    const int row0 = blockIdx.y * 128, col0 = blockIdx.x * 128;

    // loader mapping: 4 groups of 64 threads, 2 rows each, 16 bf16 (32B) per row
    const int arr = tid >> 6;              // 0:Ah 1:Al 2:Bh 3:Bl
    const int r2  = (tid & 63) * 2;
    const __nv_bfloat16* g0 = (arr == 0) ? Ah_ : (arr == 1) ? Al_ : (arr == 2) ? Wh_ : Wl_;
    const __nv_bfloat16* gp = g0 + (size_t)((arr < 2 ? row0 : col0) + r2) * KDIM;

    // fragment lane decomposition (PTX m16n8k16 layout)
    const int qm  = lane >> 2;             // row within 8-row group
    const int qk  = (lane & 3) * 2;        // k element pair base

    float acc[2][8][4];
#pragma unroll
    for (int i = 0; i < 2; i++)
#pragma unroll
        for (int j = 0; j < 8; j++)
#pragma unroll
            for (int q = 0; q < 4; q++) acc[i][j][q] = 0.f;

    constexpr int NS = KDIM / 16;
    for (int t = 0; t < NS; t++) {
        const int kc = t * 16;
        const uint4 v0 = *(const uint4*)(gp + kc);
        const uint4 v1 = *(const uint4*)(gp + kc + 8);
        const uint4 v2 = *(const uint4*)(gp + KDIM + kc);
        const uint4 v3 = *(const uint4*)(gp + KDIM + kc + 8);
        __syncthreads();                                    // prev-iter reads done
        *(uint4*)&sm[arr][r2][0]     = v0;
        *(uint4*)&sm[arr][r2][8]     = v1;
        *(uint4*)&sm[arr][r2 + 1][0] = v2;
        *(uint4*)&sm[arr][r2 + 1][8] = v3;
        __syncthreads();                                    // stage visible

        uint32_t bH[8][2], bL[8][2];
#pragma unroll
        for (int nt = 0; nt < 8; nt++) {
            const int n = warp_n * 64 + nt * 8 + qm;
            bH[nt][0] = *(const uint32_t*)&sm[2][n][qk];
            bH[nt][1] = *(const uint32_t*)&sm[2][n][qk + 8];
            bL[nt][0] = *(const uint32_t*)&sm[3][n][qk];
            bL[nt][1] = *(const uint32_t*)&sm[3][n][qk + 8];
        }
#pragma unroll
        for (int mt = 0; mt < 2; mt++) {
            const int m = warp_m * 32 + mt * 16 + qm;
            uint32_t aH[4], aL[4];
            aH[0] = *(const uint32_t*)&sm[0][m][qk];
            aH[1] = *(const uint32_t*)&sm[0][m + 8][qk];
            aH[2] = *(const uint32_t*)&sm[0][m][qk + 8];
            aH[3] = *(const uint32_t*)&sm[0][m + 8][qk + 8];
            aL[0] = *(const uint32_t*)&sm[1][m][qk];
            aL[1] = *(const uint32_t*)&sm[1][m + 8][qk];
            aL[2] = *(const uint32_t*)&sm[1][m][qk + 8];
            aL[3] = *(const uint32_t*)&sm[1][m + 8][qk + 8];
#pragma unroll
            for (int nt = 0; nt < 8; nt++) {
                mma16816(acc[mt][nt], aH, bH[nt]);
                mma16816(acc[mt][nt], aL, bH[nt]);
                mma16816(acc[mt][nt], aH, bL[nt]);
            }
        }
    }

    // epilogue: c0,c1 at (m = qm, n = qk), c2,c3 at m+8
#pragma unroll
    for (int mt = 0; mt < 2; mt++) {
#pragma unroll
        for (int nt = 0; nt < 8; nt++) {
            const int r = row0 + warp_m * 32 + mt * 16 + qm;
            const int c = col0 + warp_n * 64 + nt * 8 + qk;
            *(float2*)&C[(size_t)r * OC + c]       = make_float2(acc[mt][nt][0], acc[mt][nt][1]);
            *(float2*)&C[(size_t)(r + 8) * OC + c] = make_float2(acc[mt][nt][2], acc[mt][nt][3]);
        }
    }
}

// device-side binding of the global scratch buffers (THE FIX)
__global__ __launch_bounds__(256, 2) void k_gemm1_mma() {
    gemm_body<KIN>(g_featH, g_featL, g_w1h, g_w1l, g_h1);
}
__global__ __launch_bounds__(256, 2) void k_gemm2_mma() {
    gemm_body<OC>(g_h1H, g_h1L, g_w2h, g_w2l, g_h2);
}

// ---------------- BN stats: deterministic two-pass partial reduction ----------------
__device__ __forceinline__ void stats_body(const float* __restrict__ h,
                                           float* __restrict__ psum,
                                           float* __restrict__ psq) {
    const int c = threadIdx.x;
    const size_t r0 = (size_t)blockIdx.x * 256;
    const float* p = h + r0 * OC + c;
    float s = 0.f, q = 0.f;
#pragma unroll 4
    for (int i = 0; i < 256; i++) {
        const float v = p[(size_t)i * OC];
        s += v;
        q = fmaf(v, v, q);
    }
    psum[blockIdx.x * OC + c] = s;
    psq[blockIdx.x * OC + c]  = q;
}
__global__ void k_stats1() { stats_body(g_h1, g_ps1, g_pq1); }
__global__ void k_stats2() { stats_body(g_h2, g_ps2, g_pq2); }

__device__ __forceinline__ void fin_body(const float* __restrict__ psum,
                                         const float* __restrict__ psq,
                                         const float* __restrict__ gamma,
                                         const float* __restrict__ beta,
                                         float* __restrict__ scale,
                                         float* __restrict__ bias) {
    const int c = threadIdx.x;
    float s = 0.f, q = 0.f;
    for (int i = 0; i < 256; i++) { s += psum[i * OC + c]; q += psq[i * OC + c]; }
    const float invN = 1.f / (float)ROWS;
    const float mean = s * invN;
    const float var  = q * invN - mean * mean;
    const float sc   = gamma[c] * rsqrtf(var + EPSBN);
    scale[c] = sc;
    bias[c]  = fmaf(-mean, sc, beta[c]);
}
__global__ void k_fin1(const float* __restrict__ g, const float* __restrict__ b) {
    fin_body(g_ps1, g_pq1, g, b, g_scale1, g_bias1);
}
__global__ void k_fin2(const float* __restrict__ g, const float* __restrict__ b) {
    fin_body(g_ps2, g_pq2, g, b, g_scale2, g_bias2);
}

// ---------------- BN1+ReLU -> split-bf16 GEMM2 input ----------------
__global__ void k_bnrelu1() {
    const size_t idx = ((size_t)blockIdx.x * 256 + threadIdx.x) * 4;
    const int c0 = (int)(idx & (OC - 1));
    const float4 v  = *(const float4*)(g_h1 + idx);
    const float4 sc = *(const float4*)(g_scale1 + c0);
    const float4 bi = *(const float4*)(g_bias1 + c0);
    float r[4];
    r[0] = fmaxf(fmaf(v.x, sc.x, bi.x), 0.f);
    r[1] = fmaxf(fmaf(v.y, sc.y, bi.y), 0.f);
    r[2] = fmaxf(fmaf(v.z, sc.z, bi.z), 0.f);
    r[3] = fmaxf(fmaf(v.w, sc.w, bi.w), 0.f);
    union { __nv_bfloat16 b4[4]; uint2 u; } uh, ul;
#pragma unroll
    for (int q = 0; q < 4; q++) split_bf16(r[q], uh.b4[q], ul.b4[q]);
    *(uint2*)(g_h1H + idx) = uh.u;
    *(uint2*)(g_h1L + idx) = ul.u;
}

// ---------------- BN2+ReLU + transpose to (B, 256, N) ----------------
__global__ void k_out(float* __restrict__ out) {
    __shared__ float tile[32][33];
    const int b  = blockIdx.z;
    const int n0 = blockIdx.x * 32, c0 = blockIdx.y * 32;
    const int tx = threadIdx.x, ty = threadIdx.y;
#pragma unroll
    for (int i = 0; i < 4; i++) {
        const int n = n0 + ty + i * 8, c = c0 + tx;
        const float v = g_h2[(size_t)(b * NPTS + n) * OC + c];
        tile[ty + i * 8][tx] = fmaxf(fmaf(v, g_scale2[c], g_bias2[c]), 0.f);
    }
    __syncthreads();
    float* o = out + (size_t)b * OC * NPTS;
#pragma unroll
    for (int i = 0; i < 4; i++)
        o[(size_t)(c0 + ty + i * 8) * NPTS + n0 + tx] = tile[tx][ty + i * 8];
}

// ---------------- launch (only harness pointers cross the host/device boundary) ----
extern "C" void kernel_launch(void* const* d_in, const int* in_sizes, int n_in,
                              void* d_out, int out_size) {
    const float* xyz1    = (const float*)d_in[0];
    const float* xyz2    = (const float*)d_in[1];
    const float* points1 = (const float*)d_in[2];
    const float* points2 = (const float*)d_in[3];
    const float* W1      = (const float*)d_in[4];
    const float* gamma1  = (const float*)d_in[5];
    const float* beta1   = (const float*)d_in[6];
    const float* W2      = (const float*)d_in[7];
    const float* gamma2  = (const float*)d_in[8];
    const float* beta2   = (const float*)d_in[9];
    float* out = (float*)d_out;

    k_transpose_p2<<<dim3(MPTS / 32, C2CH / 32, BB), dim3(32, 8)>>>(points2);
    k_knn<<<dim3(NPTS / 256, BB), 256>>>(xyz1, xyz2);
    k_interp<<<ROWS / 4, 128>>>();
    k_transpose_p1<<<dim3(NPTS / 32, C1CH / 32, BB), dim3(32, 8)>>>(points1);
    k_prep_w<<<(OC * KIN + 255) / 256, 256>>>(W1, W2);

    k_gemm1_mma<<<dim3(OC / 128, ROWS / 128), 256>>>();
    k_stats1<<<256, 256>>>();
    k_fin1<<<1, 256>>>(gamma1, beta1);
    k_bnrelu1<<<(ROWS * OC) / 1024, 256>>>();

    k_gemm2_mma<<<dim3(OC / 128, ROWS / 128), 256>>>();
    k_stats2<<<256, 256>>>();
    k_fin2<<<1, 256>>>(gamma2, beta2);

    k_out<<<dim3(NPTS / 32, OC / 32, BB), dim3(32, 8)>>>(out);
}

// round 13
// speedup vs baseline: 2.2575x; 1.0845x over previous
#include <cuda_runtime.h>
#include <cuda_bf16.h>
#include <cstdint>

// ---------------- problem constants ----------------
#define BB    16
#define NPTS  4096
#define MPTS  1024
#define C1CH  128
#define C2CH  256
#define KIN   384          // C1 + C2
#define OC    256          // MLP0 == MLP1 == 256
#define ROWS  (BB * NPTS)  // 65536
#define EPSBN 1e-5f

// ---------------- device scratch (static, allocation-free, 16B aligned) ----------------
__device__ __align__(16) float g_p2t[BB * MPTS * C2CH];
__device__ __align__(16) __nv_bfloat16 g_featH[ROWS * KIN];
__device__ __align__(16) __nv_bfloat16 g_featL[ROWS * KIN];
__device__ __align__(16) int   g_idx[ROWS * 3];
__device__ __align__(16) float g_wgt[ROWS * 3];
__device__ __align__(16) float g_h1[ROWS * OC];
__device__ __align__(16) __nv_bfloat16 g_h1H[ROWS * OC];
__device__ __align__(16) __nv_bfloat16 g_h1L[ROWS * OC];
__device__ __align__(16) float g_h2[ROWS * OC];
__device__ __align__(16) __nv_bfloat16 g_w1h[OC * KIN], g_w1l[OC * KIN];
__device__ __align__(16) __nv_bfloat16 g_w2h[OC * OC],  g_w2l[OC * OC];
__device__ __align__(16) float g_ps1[256 * OC], g_pq1[256 * OC];
__device__ __align__(16) float g_ps2[256 * OC], g_pq2[256 * OC];
__device__ __align__(16) float g_scale1[OC], g_bias1[OC];
__device__ __align__(16) float g_scale2[OC], g_bias2[OC];

// ---------------- helpers ----------------
__device__ __forceinline__ uint32_t smem_u32(const void* p) {
    uint32_t a;
    asm("{ .reg .u64 t; cvta.to.shared.u64 t, %1; cvt.u32.u64 %0, t; }" : "=r"(a) : "l"(p));
    return a;
}
#define CP16(dst, src) \
    asm volatile("cp.async.cg.shared.global [%0], [%1], 16;" :: "r"(dst), "l"(src) : "memory")
#define CP_COMMIT()  asm volatile("cp.async.commit_group;" ::: "memory")
#define CP_WAIT0()   asm volatile("cp.async.wait_group 0;" ::: "memory")

__device__ __forceinline__ void mma16816(float* d, const uint32_t* a, const uint32_t* b) {
    asm volatile("mma.sync.aligned.m16n8k16.row.col.f32.bf16.bf16.f32 "
        "{%0,%1,%2,%3}, {%4,%5,%6,%7}, {%8,%9}, {%0,%1,%2,%3};"
        : "+f"(d[0]), "+f"(d[1]), "+f"(d[2]), "+f"(d[3])
        : "r"(a[0]), "r"(a[1]), "r"(a[2]), "r"(a[3]), "r"(b[0]), "r"(b[1]));
}

__device__ __forceinline__ void split_bf16(float v, __nv_bfloat16& h, __nv_bfloat16& l) {
    h = __float2bfloat16(v);
    l = __float2bfloat16(v - __bfloat162float(h));
}

// ---------------- transpose points2: (B, C2, M) -> (B, M, C2) ----------------
__global__ void k_transpose_p2(const float* __restrict__ p2) {
    __shared__ float tile[32][33];
    const int b  = blockIdx.z;
    const int m0 = blockIdx.x * 32, c0 = blockIdx.y * 32;
    const int tx = threadIdx.x, ty = threadIdx.y;
    const float* in = p2 + (size_t)b * C2CH * MPTS;
#pragma unroll
    for (int i = 0; i < 4; i++)
        tile[ty + i * 8][tx] = in[(size_t)(c0 + ty + i * 8) * MPTS + m0 + tx];
    __syncthreads();
    float* out = g_p2t + (size_t)b * MPTS * C2CH;
#pragma unroll
    for (int i = 0; i < 4; i++)
        out[(size_t)(m0 + ty + i * 8) * C2CH + c0 + tx] = tile[tx][ty + i * 8];
}

// ---------------- transpose points1 -> split-bf16 feat cols [256..384) ----------------
__global__ void k_transpose_p1(const float* __restrict__ p1) {
    __shared__ float tile[32][33];
    const int b  = blockIdx.z;
    const int n0 = blockIdx.x * 32, c0 = blockIdx.y * 32;
    const int tx = threadIdx.x, ty = threadIdx.y;
    const float* in = p1 + (size_t)b * C1CH * NPTS;
#pragma unroll
    for (int i = 0; i < 4; i++)
        tile[ty + i * 8][tx] = in[(size_t)(c0 + ty + i * 8) * NPTS + n0 + tx];
    __syncthreads();
#pragma unroll
    for (int i = 0; i < 4; i++) {
        const int n = n0 + ty + i * 8;
        const size_t o = (size_t)(b * NPTS + n) * KIN + C2CH + c0 + tx;
        __nv_bfloat16 h, l;
        split_bf16(tile[tx][ty + i * 8], h, l);
        g_featH[o] = h; g_featL[o] = l;
    }
}

// ---------------- 3-NN over M=1024 (xyz2 staged in SMEM) ----------------
__global__ void k_knn(const float* __restrict__ xyz1, const float* __restrict__ xyz2) {
    __shared__ float4 s2[MPTS];
    const int b   = blockIdx.y;
    const int tid = threadIdx.x;
    const float* x2 = xyz2 + (size_t)b * 3 * MPTS;
    for (int m = tid; m < MPTS; m += 256)
        s2[m] = make_float4(x2[m], x2[m + MPTS], x2[m + 2 * MPTS], 0.f);
    __syncthreads();

    const int n = blockIdx.x * 256 + tid;
    const float* x1 = xyz1 + (size_t)b * 3 * NPTS;
    const float px = x1[n], py = x1[n + NPTS], pz = x1[n + 2 * NPTS];

    float d0 = 3.4e38f, d1 = 3.4e38f, d2 = 3.4e38f;
    int   i0 = 0, i1 = 0, i2 = 0;
#pragma unroll 4
    for (int m = 0; m < MPTS; m++) {
        const float4 q = s2[m];
        const float dx = px - q.x, dy = py - q.y, dz = pz - q.z;
        const float d = fmaf(dx, dx, fmaf(dy, dy, dz * dz));
        if (d < d2) {
            if (d < d1) {
                d2 = d1; i2 = i1;
                if (d < d0) { d1 = d0; i1 = i0; d0 = d; i0 = m; }
                else        { d1 = d;  i1 = m; }
            } else { d2 = d; i2 = m; }
        }
    }
    d0 = fmaxf(d0, 1e-10f); d1 = fmaxf(d1, 1e-10f); d2 = fmaxf(d2, 1e-10f);
    const float w0 = 1.f / d0, w1 = 1.f / d1, w2 = 1.f / d2;
    const float inv = 1.f / (w0 + w1 + w2);
    const int row = b * NPTS + n;
    g_idx[row * 3 + 0] = i0; g_idx[row * 3 + 1] = i1; g_idx[row * 3 + 2] = i2;
    g_wgt[row * 3 + 0] = w0 * inv; g_wgt[row * 3 + 1] = w1 * inv; g_wgt[row * 3 + 2] = w2 * inv;
}

// -------- weighted gather -> split-bf16 feat cols [0..256) (warp per row) --------
__global__ void k_interp() {
    const int tid  = threadIdx.x;
    const int warp = tid >> 5, lane = tid & 31;
    const int row  = blockIdx.x * 4 + warp;
    const int b    = row >> 12;
    const int i0 = g_idx[row * 3 + 0], i1 = g_idx[row * 3 + 1], i2 = g_idx[row * 3 + 2];
    const float w0 = g_wgt[row * 3 + 0], w1 = g_wgt[row * 3 + 1], w2 = g_wgt[row * 3 + 2];
    const float4* f0 = (const float4*)(g_p2t + ((size_t)b * MPTS + i0) * C2CH);
    const float4* f1 = (const float4*)(g_p2t + ((size_t)b * MPTS + i1) * C2CH);
    const float4* f2 = (const float4*)(g_p2t + ((size_t)b * MPTS + i2) * C2CH);
    union { __nv_bfloat16 b8[8]; uint4 u; } uh, ul;
#pragma unroll
    for (int half = 0; half < 2; half++) {
        const int j = lane * 2 + half;
        const float4 a = f0[j], c = f1[j], e = f2[j];
        float r[4];
        r[0] = fmaf(w0, a.x, fmaf(w1, c.x, w2 * e.x));
        r[1] = fmaf(w0, a.y, fmaf(w1, c.y, w2 * e.y));
        r[2] = fmaf(w0, a.z, fmaf(w1, c.z, w2 * e.z));
        r[3] = fmaf(w0, a.w, fmaf(w1, c.w, w2 * e.w));
#pragma unroll
        for (int q = 0; q < 4; q++)
            split_bf16(r[q], uh.b8[half * 4 + q], ul.b8[half * 4 + q]);
    }
    const size_t o = (size_t)row * KIN + lane * 8;
    *(uint4*)(g_featH + o) = uh.u;
    *(uint4*)(g_featL + o) = ul.u;
}

// ---------------- weight split prep ----------------
__global__ void k_prep_w(const float* __restrict__ W1, const float* __restrict__ W2) {
    const int i = blockIdx.x * 256 + threadIdx.x;
    if (i < OC * KIN) split_bf16(W1[i], g_w1h[i], g_w1l[i]);
    if (i < OC * OC)  split_bf16(W2[i], g_w2h[i], g_w2l[i]);
}

// ---------------- bf16x3-split GEMM via mma.sync: C = A(ROWSxK) * W(OCxK)^T ----
// CTA 128x128, 8 warps (4m x 2n), warp tile 32x64. K=16 stages, DOUBLE-buffered
// SMEM (2 x 24KB = 48KB static) filled by cp.async: one __syncthreads per stage,
// stage t+1's global latency hidden behind compute(t). 48B-padded rows keep the
// direct-LDS fragment loads conflict-free (verified R10). Pointers bound in
// device code via the __global__ wrappers (host-side __device__-symbol decay
// was the R5/R8 failure).
template <int KDIM>
__device__ __forceinline__ void gemm_body(
        const __nv_bfloat16* __restrict__ Ah_, const __nv_bfloat16* __restrict__ Al_,
        const __nv_bfloat16* __restrict__ Wh_, const __nv_bfloat16* __restrict__ Wl_,
        float* __restrict__ C) {
    __shared__ __align__(16) __nv_bfloat16 sm[2][4][128][24];   // [buf][Ah|Al|Bh|Bl]
    const int tid  = threadIdx.x;
    const int lane = tid & 31, wid = tid >> 5;
    const int warp_m = wid & 3, warp_n = wid >> 2;
    const int row0 = blockIdx.y * 128, col0 = blockIdx.x * 128;

    // loader mapping: 4 groups of 64 threads, 2 rows each, 16 bf16 (32B) per row
    const int arr = tid >> 6;              // 0:Ah 1:Al 2:Bh 3:Bl
    const int r2  = (tid & 63) * 2;
    const __nv_bfloat16* g0 = (arr == 0) ? Ah_ : (arr == 1) ? Al_ : (arr == 2) ? Wh_ : Wl_;
    const __nv_bfloat16* gp = g0 + (size_t)((arr < 2 ? row0 : col0) + r2) * KDIM;

    // cp.async destination (32-bit shared address); strides in bytes
    const uint32_t sdst0 = smem_u32(&sm[0][arr][r2][0]);
    const int BUFB = 4 * 128 * 24 * 2;     // 24576

    // fragment lane decomposition (PTX m16n8k16 layout)
    const int qm  = lane >> 2;             // row within 8-row group
    const int qk  = (lane & 3) * 2;        // k element pair base

    float acc[2][8][4];
#pragma unroll
    for (int i = 0; i < 2; i++)
#pragma unroll
        for (int j = 0; j < 8; j++)
#pragma unroll
            for (int q = 0; q < 4; q++) acc[i][j][q] = 0.f;

    // prologue: stage 0 -> buf 0
    CP16(sdst0,      gp);
    CP16(sdst0 + 16, gp + 8);
    CP16(sdst0 + 48, gp + KDIM);
    CP16(sdst0 + 64, gp + KDIM + 8);
    CP_COMMIT();

    constexpr int NS = KDIM / 16;
    for (int t = 0; t < NS; t++) {
        const int buf = t & 1;
        CP_WAIT0();                 // own stage-t copies complete
        __syncthreads();            // ...and everyone's; also fences buf^1 reuse
        if (t + 1 < NS) {
            const uint32_t d = sdst0 + (buf ^ 1) * BUFB;
            const __nv_bfloat16* gs = gp + (t + 1) * 16;
            CP16(d,      gs);
            CP16(d + 16, gs + 8);
            CP16(d + 48, gs + KDIM);
            CP16(d + 64, gs + KDIM + 8);
            CP_COMMIT();
        }

        const __nv_bfloat16 (*S)[128][24] = sm[buf];
        uint32_t bH[8][2], bL[8][2];
#pragma unroll
        for (int nt = 0; nt < 8; nt++) {
            const int n = warp_n * 64 + nt * 8 + qm;
            bH[nt][0] = *(const uint32_t*)&S[2][n][qk];
            bH[nt][1] = *(const uint32_t*)&S[2][n][qk + 8];
            bL[nt][0] = *(const uint32_t*)&S[3][n][qk];
            bL[nt][1] = *(const uint32_t*)&S[3][n][qk + 8];
        }
#pragma unroll
        for (int mt = 0; mt < 2; mt++) {
            const int m = warp_m * 32 + mt * 16 + qm;
            uint32_t aH[4], aL[4];
            aH[0] = *(const uint32_t*)&S[0][m][qk];
            aH[1] = *(const uint32_t*)&S[0][m + 8][qk];
            aH[2] = *(const uint32_t*)&S[0][m][qk + 8];
            aH[3] = *(const uint32_t*)&S[0][m + 8][qk + 8];
            aL[0] = *(const uint32_t*)&S[1][m][qk];
            aL[1] = *(const uint32_t*)&S[1][m + 8][qk];
            aL[2] = *(const uint32_t*)&S[1][m][qk + 8];
            aL[3] = *(const uint32_t*)&S[1][m + 8][qk + 8];
#pragma unroll
            for (int nt = 0; nt < 8; nt++) {
                mma16816(acc[mt][nt], aH, bH[nt]);
                mma16816(acc[mt][nt], aL, bH[nt]);
                mma16816(acc[mt][nt], aH, bL[nt]);
            }
        }
    }

    // epilogue: c0,c1 at (m = qm, n = qk), c2,c3 at m+8
#pragma unroll
    for (int mt = 0; mt < 2; mt++) {
#pragma unroll
        for (int nt = 0; nt < 8; nt++) {
            const int r = row0 + warp_m * 32 + mt * 16 + qm;
            const int c = col0 + warp_n * 64 + nt * 8 + qk;
            *(float2*)&C[(size_t)r * OC + c]       = make_float2(acc[mt][nt][0], acc[mt][nt][1]);
            *(float2*)&C[(size_t)(r + 8) * OC + c] = make_float2(acc[mt][nt][2], acc[mt][nt][3]);
        }
    }
}

// device-side binding of the global scratch buffers
__global__ __launch_bounds__(256, 2) void k_gemm1_mma() {
    gemm_body<KIN>(g_featH, g_featL, g_w1h, g_w1l, g_h1);
}
__global__ __launch_bounds__(256, 2) void k_gemm2_mma() {
    gemm_body<OC>(g_h1H, g_h1L, g_w2h, g_w2l, g_h2);
}

// ---------------- BN stats: deterministic two-pass partial reduction ----------------
__device__ __forceinline__ void stats_body(const float* __restrict__ h,
                                           float* __restrict__ psum,
                                           float* __restrict__ psq) {
    const int c = threadIdx.x;
    const size_t r0 = (size_t)blockIdx.x * 256;
    const float* p = h + r0 * OC + c;
    float s = 0.f, q = 0.f;
#pragma unroll 4
    for (int i = 0; i < 256; i++) {
        const float v = p[(size_t)i * OC];
        s += v;
        q = fmaf(v, v, q);
    }
    psum[blockIdx.x * OC + c] = s;
    psq[blockIdx.x * OC + c]  = q;
}
__global__ void k_stats1() { stats_body(g_h1, g_ps1, g_pq1); }
__global__ void k_stats2() { stats_body(g_h2, g_ps2, g_pq2); }

__device__ __forceinline__ void fin_body(const float* __restrict__ psum,
                                         const float* __restrict__ psq,
                                         const float* __restrict__ gamma,
                                         const float* __restrict__ beta,
                                         float* __restrict__ scale,
                                         float* __restrict__ bias) {
    const int c = threadIdx.x;
    float s = 0.f, q = 0.f;
    for (int i = 0; i < 256; i++) { s += psum[i * OC + c]; q += psq[i * OC + c]; }
    const float invN = 1.f / (float)ROWS;
    const float mean = s * invN;
    const float var  = q * invN - mean * mean;
    const float sc   = gamma[c] * rsqrtf(var + EPSBN);
    scale[c] = sc;
    bias[c]  = fmaf(-mean, sc, beta[c]);
}
__global__ void k_fin1(const float* __restrict__ g, const float* __restrict__ b) {
    fin_body(g_ps1, g_pq1, g, b, g_scale1, g_bias1);
}
__global__ void k_fin2(const float* __restrict__ g, const float* __restrict__ b) {
    fin_body(g_ps2, g_pq2, g, b, g_scale2, g_bias2);
}

// ---------------- BN1+ReLU -> split-bf16 GEMM2 input ----------------
__global__ void k_bnrelu1() {
    const size_t idx = ((size_t)blockIdx.x * 256 + threadIdx.x) * 4;
    const int c0 = (int)(idx & (OC - 1));
    const float4 v  = *(const float4*)(g_h1 + idx);
    const float4 sc = *(const float4*)(g_scale1 + c0);
    const float4 bi = *(const float4*)(g_bias1 + c0);
    float r[4];
    r[0] = fmaxf(fmaf(v.x, sc.x, bi.x), 0.f);
    r[1] = fmaxf(fmaf(v.y, sc.y, bi.y), 0.f);
    r[2] = fmaxf(fmaf(v.z, sc.z, bi.z), 0.f);
    r[3] = fmaxf(fmaf(v.w, sc.w, bi.w), 0.f);
    union { __nv_bfloat16 b4[4]; uint2 u; } uh, ul;
#pragma unroll
    for (int q = 0; q < 4; q++) split_bf16(r[q], uh.b4[q], ul.b4[q]);
    *(uint2*)(g_h1H + idx) = uh.u;
    *(uint2*)(g_h1L + idx) = ul.u;
}

// ---------------- BN2+ReLU + transpose to (B, 256, N) ----------------
__global__ void k_out(float* __restrict__ out) {
    __shared__ float tile[32][33];
    const int b  = blockIdx.z;
    const int n0 = blockIdx.x * 32, c0 = blockIdx.y * 32;
    const int tx = threadIdx.x, ty = threadIdx.y;
#pragma unroll
    for (int i = 0; i < 4; i++) {
        const int n = n0 + ty + i * 8, c = c0 + tx;
        const float v = g_h2[(size_t)(b * NPTS + n) * OC + c];
        tile[ty + i * 8][tx] = fmaxf(fmaf(v, g_scale2[c], g_bias2[c]), 0.f);
    }
    __syncthreads();
    float* o = out + (size_t)b * OC * NPTS;
#pragma unroll
    for (int i = 0; i < 4; i++)
        o[(size_t)(c0 + ty + i * 8) * NPTS + n0 + tx] = tile[tx][ty + i * 8];
}

// ---------------- launch (only harness pointers cross the host/device boundary) ----
extern "C" void kernel_launch(void* const* d_in, const int* in_sizes, int n_in,
                              void* d_out, int out_size) {
    const float* xyz1    = (const float*)d_in[0];
    const float* xyz2    = (const float*)d_in[1];
    const float* points1 = (const float*)d_in[2];
    const float* points2 = (const float*)d_in[3];
    const float* W1      = (const float*)d_in[4];
    const float* gamma1  = (const float*)d_in[5];
    const float* beta1   = (const float*)d_in[6];
    const float* W2      = (const float*)d_in[7];
    const float* gamma2  = (const float*)d_in[8];
    const float* beta2   = (const float*)d_in[9];
    float* out = (float*)d_out;

    k_transpose_p2<<<dim3(MPTS / 32, C2CH / 32, BB), dim3(32, 8)>>>(points2);
    k_knn<<<dim3(NPTS / 256, BB), 256>>>(xyz1, xyz2);
    k_interp<<<ROWS / 4, 128>>>();
    k_transpose_p1<<<dim3(NPTS / 32, C1CH / 32, BB), dim3(32, 8)>>>(points1);
    k_prep_w<<<(OC * KIN + 255) / 256, 256>>>(W1, W2);

    k_gemm1_mma<<<dim3(OC / 128, ROWS / 128), 256>>>();
    k_stats1<<<256, 256>>>();
    k_fin1<<<1, 256>>>(gamma1, beta1);
    k_bnrelu1<<<(ROWS * OC) / 1024, 256>>>();

    k_gemm2_mma<<<dim3(OC / 128, ROWS / 128), 256>>>();
    k_stats2<<<256, 256>>>();
    k_fin2<<<1, 256>>>(gamma2, beta2);

    k_out<<<dim3(NPTS / 32, OC / 32, BB), dim3(32, 8)>>>(out);
}

// round 14
// speedup vs baseline: 2.5740x; 1.1402x over previous
#include <cuda_runtime.h>
#include <cuda_bf16.h>
#include <cstdint>

// ---------------- problem constants ----------------
#define BB    16
#define NPTS  4096
#define MPTS  1024
#define C1CH  128
#define C2CH  256
#define KIN   384          // C1 + C2
#define OC    256          // MLP0 == MLP1 == 256
#define ROWS  (BB * NPTS)  // 65536
#define EPSBN 1e-5f
#define NBLK  512          // GEMM row-blocks (ROWS/128) -> BN partial count

// ---------------- device scratch (static, allocation-free, 16B aligned) ----------------
__device__ __align__(16) float g_p2t[BB * MPTS * C2CH];
__device__ __align__(16) __nv_bfloat16 g_featH[ROWS * KIN];
__device__ __align__(16) __nv_bfloat16 g_featL[ROWS * KIN];
__device__ __align__(16) int   g_idx[ROWS * 3];
__device__ __align__(16) float g_wgt[ROWS * 3];
__device__ __align__(16) float g_h1[ROWS * OC];
__device__ __align__(16) __nv_bfloat16 g_h1H[ROWS * OC];
__device__ __align__(16) __nv_bfloat16 g_h1L[ROWS * OC];
__device__ __align__(16) float g_h2[ROWS * OC];
__device__ __align__(16) __nv_bfloat16 g_w1h[OC * KIN], g_w1l[OC * KIN];
__device__ __align__(16) __nv_bfloat16 g_w2h[OC * OC],  g_w2l[OC * OC];
__device__ __align__(16) float g_ps1[NBLK * OC], g_pq1[NBLK * OC];
__device__ __align__(16) float g_ps2[NBLK * OC], g_pq2[NBLK * OC];
__device__ __align__(16) float g_scale1[OC], g_bias1[OC];
__device__ __align__(16) float g_scale2[OC], g_bias2[OC];

// ---------------- helpers ----------------
__device__ __forceinline__ uint32_t smem_u32(const void* p) {
    uint32_t a;
    asm("{ .reg .u64 t; cvta.to.shared.u64 t, %1; cvt.u32.u64 %0, t; }" : "=r"(a) : "l"(p));
    return a;
}
#define CP16(dst, src) \
    asm volatile("cp.async.cg.shared.global [%0], [%1], 16;" :: "r"(dst), "l"(src) : "memory")
#define CP_COMMIT()  asm volatile("cp.async.commit_group;" ::: "memory")
#define CP_WAIT0()   asm volatile("cp.async.wait_group 0;" ::: "memory")

__device__ __forceinline__ void ldm_x4(uint32_t* r, uint32_t addr) {
    asm volatile("ldmatrix.sync.aligned.m8n8.x4.shared.b16 {%0,%1,%2,%3}, [%4];"
        : "=r"(r[0]), "=r"(r[1]), "=r"(r[2]), "=r"(r[3]) : "r"(addr));
}

__device__ __forceinline__ void mma16816(float* d, const uint32_t* a, const uint32_t* b) {
    asm volatile("mma.sync.aligned.m16n8k16.row.col.f32.bf16.bf16.f32 "
        "{%0,%1,%2,%3}, {%4,%5,%6,%7}, {%8,%9}, {%0,%1,%2,%3};"
        : "+f"(d[0]), "+f"(d[1]), "+f"(d[2]), "+f"(d[3])
        : "r"(a[0]), "r"(a[1]), "r"(a[2]), "r"(a[3]), "r"(b[0]), "r"(b[1]));
}

__device__ __forceinline__ void split_bf16(float v, __nv_bfloat16& h, __nv_bfloat16& l) {
    h = __float2bfloat16(v);
    l = __float2bfloat16(v - __bfloat162float(h));
}

// ---------------- transpose points2: (B, C2, M) -> (B, M, C2) ----------------
__global__ void k_transpose_p2(const float* __restrict__ p2) {
    __shared__ float tile[32][33];
    const int b  = blockIdx.z;
    const int m0 = blockIdx.x * 32, c0 = blockIdx.y * 32;
    const int tx = threadIdx.x, ty = threadIdx.y;
    const float* in = p2 + (size_t)b * C2CH * MPTS;
#pragma unroll
    for (int i = 0; i < 4; i++)
        tile[ty + i * 8][tx] = in[(size_t)(c0 + ty + i * 8) * MPTS + m0 + tx];
    __syncthreads();
    float* out = g_p2t + (size_t)b * MPTS * C2CH;
#pragma unroll
    for (int i = 0; i < 4; i++)
        out[(size_t)(m0 + ty + i * 8) * C2CH + c0 + tx] = tile[tx][ty + i * 8];
}

// ---------------- transpose points1 -> split-bf16 feat cols [256..384) ----------------
__global__ void k_transpose_p1(const float* __restrict__ p1) {
    __shared__ float tile[32][33];
    const int b  = blockIdx.z;
    const int n0 = blockIdx.x * 32, c0 = blockIdx.y * 32;
    const int tx = threadIdx.x, ty = threadIdx.y;
    const float* in = p1 + (size_t)b * C1CH * NPTS;
#pragma unroll
    for (int i = 0; i < 4; i++)
        tile[ty + i * 8][tx] = in[(size_t)(c0 + ty + i * 8) * NPTS + n0 + tx];
    __syncthreads();
#pragma unroll
    for (int i = 0; i < 4; i++) {
        const int n = n0 + ty + i * 8;
        const size_t o = (size_t)(b * NPTS + n) * KIN + C2CH + c0 + tx;
        __nv_bfloat16 h, l;
        split_bf16(tile[tx][ty + i * 8], h, l);
        g_featH[o] = h; g_featL[o] = l;
    }
}

// ---------------- 3-NN over M=1024 (xyz2 staged in SMEM) ----------------
__global__ void k_knn(const float* __restrict__ xyz1, const float* __restrict__ xyz2) {
    __shared__ float4 s2[MPTS];
    const int b   = blockIdx.y;
    const int tid = threadIdx.x;
    const float* x2 = xyz2 + (size_t)b * 3 * MPTS;
    for (int m = tid; m < MPTS; m += 256)
        s2[m] = make_float4(x2[m], x2[m + MPTS], x2[m + 2 * MPTS], 0.f);
    __syncthreads();

    const int n = blockIdx.x * 256 + tid;
    const float* x1 = xyz1 + (size_t)b * 3 * NPTS;
    const float px = x1[n], py = x1[n + NPTS], pz = x1[n + 2 * NPTS];

    float d0 = 3.4e38f, d1 = 3.4e38f, d2 = 3.4e38f;
    int   i0 = 0, i1 = 0, i2 = 0;
#pragma unroll 4
    for (int m = 0; m < MPTS; m++) {
        const float4 q = s2[m];
        const float dx = px - q.x, dy = py - q.y, dz = pz - q.z;
        const float d = fmaf(dx, dx, fmaf(dy, dy, dz * dz));
        if (d < d2) {
            if (d < d1) {
                d2 = d1; i2 = i1;
                if (d < d0) { d1 = d0; i1 = i0; d0 = d; i0 = m; }
                else        { d1 = d;  i1 = m; }
            } else { d2 = d; i2 = m; }
        }
    }
    d0 = fmaxf(d0, 1e-10f); d1 = fmaxf(d1, 1e-10f); d2 = fmaxf(d2, 1e-10f);
    const float w0 = 1.f / d0, w1 = 1.f / d1, w2 = 1.f / d2;
    const float inv = 1.f / (w0 + w1 + w2);
    const int row = b * NPTS + n;
    g_idx[row * 3 + 0] = i0; g_idx[row * 3 + 1] = i1; g_idx[row * 3 + 2] = i2;
    g_wgt[row * 3 + 0] = w0 * inv; g_wgt[row * 3 + 1] = w1 * inv; g_wgt[row * 3 + 2] = w2 * inv;
}

// -------- weighted gather -> split-bf16 feat cols [0..256) (warp per row) --------
__global__ void k_interp() {
    const int tid  = threadIdx.x;
    const int warp = tid >> 5, lane = tid & 31;
    const int row  = blockIdx.x * 4 + warp;
    const int b    = row >> 12;
    const int i0 = g_idx[row * 3 + 0], i1 = g_idx[row * 3 + 1], i2 = g_idx[row * 3 + 2];
    const float w0 = g_wgt[row * 3 + 0], w1 = g_wgt[row * 3 + 1], w2 = g_wgt[row * 3 + 2];
    const float4* f0 = (const float4*)(g_p2t + ((size_t)b * MPTS + i0) * C2CH);
    const float4* f1 = (const float4*)(g_p2t + ((size_t)b * MPTS + i1) * C2CH);
    const float4* f2 = (const float4*)(g_p2t + ((size_t)b * MPTS + i2) * C2CH);
    union { __nv_bfloat16 b8[8]; uint4 u; } uh, ul;
#pragma unroll
    for (int half = 0; half < 2; half++) {
        const int j = lane * 2 + half;
        const float4 a = f0[j], c = f1[j], e = f2[j];
        float r[4];
        r[0] = fmaf(w0, a.x, fmaf(w1, c.x, w2 * e.x));
        r[1] = fmaf(w0, a.y, fmaf(w1, c.y, w2 * e.y));
        r[2] = fmaf(w0, a.z, fmaf(w1, c.z, w2 * e.z));
        r[3] = fmaf(w0, a.w, fmaf(w1, c.w, w2 * e.w));
#pragma unroll
        for (int q = 0; q < 4; q++)
            split_bf16(r[q], uh.b8[half * 4 + q], ul.b8[half * 4 + q]);
    }
    const size_t o = (size_t)row * KIN + lane * 8;
    *(uint4*)(g_featH + o) = uh.u;
    *(uint4*)(g_featL + o) = ul.u;
}

// ---------------- weight split prep ----------------
__global__ void k_prep_w(const float* __restrict__ W1, const float* __restrict__ W2) {
    const int i = blockIdx.x * 256 + threadIdx.x;
    if (i < OC * KIN) split_bf16(W1[i], g_w1h[i], g_w1l[i]);
    if (i < OC * OC)  split_bf16(W2[i], g_w2h[i], g_w2l[i]);
}

// ---------------- bf16x3-split GEMM via mma.sync: C = A(ROWSxK) * W(OCxK)^T ----
// CTA 128x128, 8 warps (4m x 2n), warp tile 32x64. K=16 stages, double-buffered
// cp.async (2x24KB = 48KB static). Fragments via ldmatrix.x4 (12 per warp-stage,
// lane map identical to the R10/R13-proven direct-LDS map; 48B row stride is
// conflict-free). Epilogue additionally emits deterministic per-CTA BN partial
// sums/sumsq (replaces the k_stats kernels' 67MB re-read passes).
#define ARR  (128 * 48)            // bytes per matrix array per buffer (6144)
#define BUFB (4 * ARR)             // 24576

template <int KDIM>
__device__ __forceinline__ void gemm_body(
        const __nv_bfloat16* __restrict__ Ah_, const __nv_bfloat16* __restrict__ Al_,
        const __nv_bfloat16* __restrict__ Wh_, const __nv_bfloat16* __restrict__ Wl_,
        float* __restrict__ C, float* __restrict__ psum, float* __restrict__ psq) {
    __shared__ __align__(16) __nv_bfloat16 sm[2][4][128][24];   // [buf][Ah|Al|Bh|Bl]
    const int tid  = threadIdx.x;
    const int lane = tid & 31, wid = tid >> 5;
    const int warp_m = wid & 3, warp_n = wid >> 2;
    const int row0 = blockIdx.y * 128, col0 = blockIdx.x * 128;

    // loader mapping: 4 groups of 64 threads, 2 rows each, 16 bf16 (32B) per row
    const int arr = tid >> 6;              // 0:Ah 1:Al 2:Bh 3:Bl
    const int r2  = (tid & 63) * 2;
    const __nv_bfloat16* g0 = (arr == 0) ? Ah_ : (arr == 1) ? Al_ : (arr == 2) ? Wh_ : Wl_;
    const __nv_bfloat16* gp = g0 + (size_t)((arr < 2 ? row0 : col0) + r2) * KDIM;
    const uint32_t sbase = smem_u32(sm);
    const uint32_t sdst0 = sbase + (uint32_t)(arr * ARR + r2 * 48);

    // ldmatrix lane addressing (byte offsets within one matrix array)
    // A: lanes 0-7 rows m+0..7 klo | 8-15 rows m+8..15 klo | 16-23 m+0..7 khi | 24-31 m+8..15 khi
    const uint32_t aoff = (uint32_t)((warp_m * 32 + (lane & 15)) * 48 + ((lane & 16) ? 16 : 0));
    // B: lanes 0-7 rows n+0..7 klo | 8-15 n+0..7 khi | 16-23 n+8..15 klo | 24-31 n+8..15 khi
    const uint32_t boff = (uint32_t)((warp_n * 64 + (lane & 7) + ((lane & 16) ? 8 : 0)) * 48
                                     + ((lane & 8) ? 16 : 0));
    // mma fragment lane decomposition (for epilogue addressing)
    const int qm = lane >> 2, qk = (lane & 3) * 2;

    float acc[2][8][4];
#pragma unroll
    for (int i = 0; i < 2; i++)
#pragma unroll
        for (int j = 0; j < 8; j++)
#pragma unroll
            for (int q = 0; q < 4; q++) acc[i][j][q] = 0.f;

    // prologue: stage 0 -> buf 0
    CP16(sdst0,      gp);
    CP16(sdst0 + 16, gp + 8);
    CP16(sdst0 + 48, gp + KDIM);
    CP16(sdst0 + 64, gp + KDIM + 8);
    CP_COMMIT();

    constexpr int NS = KDIM / 16;
    for (int t = 0; t < NS; t++) {
        const int buf = t & 1;
        CP_WAIT0();
        __syncthreads();
        if (t + 1 < NS) {
            const uint32_t d = sdst0 + (buf ^ 1) * BUFB;
            const __nv_bfloat16* gs = gp + (t + 1) * 16;
            CP16(d,      gs);
            CP16(d + 16, gs + 8);
            CP16(d + 48, gs + KDIM);
            CP16(d + 64, gs + KDIM + 8);
            CP_COMMIT();
        }

        const uint32_t sb = sbase + buf * BUFB;
        uint32_t aH[2][4], aL[2][4], bH[8][2], bL[8][2];
#pragma unroll
        for (int mt = 0; mt < 2; mt++) {
            ldm_x4(aH[mt], sb + 0 * ARR + aoff + mt * 768);   // 16 rows * 48B
            ldm_x4(aL[mt], sb + 1 * ARR + aoff + mt * 768);
        }
#pragma unroll
        for (int np = 0; np < 4; np++) {
            uint32_t q[4];
            ldm_x4(q, sb + 2 * ARR + boff + np * 768);
            bH[2 * np][0] = q[0]; bH[2 * np][1] = q[1];
            bH[2 * np + 1][0] = q[2]; bH[2 * np + 1][1] = q[3];
            ldm_x4(q, sb + 3 * ARR + boff + np * 768);
            bL[2 * np][0] = q[0]; bL[2 * np][1] = q[1];
            bL[2 * np + 1][0] = q[2]; bL[2 * np + 1][1] = q[3];
        }
#pragma unroll
        for (int mt = 0; mt < 2; mt++)
#pragma unroll
            for (int nt = 0; nt < 8; nt++) {
                mma16816(acc[mt][nt], aH[mt], bH[nt]);
                mma16816(acc[mt][nt], aL[mt], bH[nt]);
                mma16816(acc[mt][nt], aH[mt], bL[nt]);
            }
    }

    // ---- epilogue: store C ----
#pragma unroll
    for (int mt = 0; mt < 2; mt++) {
#pragma unroll
        for (int nt = 0; nt < 8; nt++) {
            const int r = row0 + warp_m * 32 + mt * 16 + qm;
            const int c = col0 + warp_n * 64 + nt * 8 + qk;
            *(float2*)&C[(size_t)r * OC + c]       = make_float2(acc[mt][nt][0], acc[mt][nt][1]);
            *(float2*)&C[(size_t)(r + 8) * OC + c] = make_float2(acc[mt][nt][2], acc[mt][nt][3]);
        }
    }

    // ---- fused deterministic BN partial stats (per-CTA col sums over 128 rows) ----
    __syncthreads();                       // all warps done reading sm -> reuse as scratch
    float* scr = (float*)sm;               // [0..511]: sums, [512..1023]: sumsq (8 warps x 64)
#pragma unroll
    for (int nt = 0; nt < 8; nt++) {
        // per-thread partials for its 2 columns (4 rows each: mt x {qm, qm+8})
        float s0 = acc[0][nt][0] + acc[0][nt][2] + acc[1][nt][0] + acc[1][nt][2];
        float s1 = acc[0][nt][1] + acc[0][nt][3] + acc[1][nt][1] + acc[1][nt][3];
        float q0 = acc[0][nt][0] * acc[0][nt][0] + acc[0][nt][2] * acc[0][nt][2]
                 + acc[1][nt][0] * acc[1][nt][0] + acc[1][nt][2] * acc[1][nt][2];
        float q1 = acc[0][nt][1] * acc[0][nt][1] + acc[0][nt][3] * acc[0][nt][3]
                 + acc[1][nt][1] * acc[1][nt][1] + acc[1][nt][3] * acc[1][nt][3];
#pragma unroll
        for (int d = 16; d >= 4; d >>= 1) {           // reduce over the 8 qm lanes
            s0 += __shfl_down_sync(0xffffffffu, s0, d);
            s1 += __shfl_down_sync(0xffffffffu, s1, d);
            q0 += __shfl_down_sync(0xffffffffu, q0, d);
            q1 += __shfl_down_sync(0xffffffffu, q1, d);
        }
        if (lane < 4) {
            const int l64 = nt * 8 + lane * 2;        // lane holds cols qk = 2*lane
            scr[wid * 64 + l64]           = s0;
            scr[wid * 64 + l64 + 1]       = s1;
            scr[512 + wid * 64 + l64]     = q0;
            scr[512 + wid * 64 + l64 + 1] = q1;
        }
    }
    __syncthreads();
    if (tid < 128) {                       // one thread per CTA-local column
        const int half = tid >> 6, l64 = tid & 63;
        float s = 0.f, q = 0.f;
#pragma unroll
        for (int wm = 0; wm < 4; wm++) {   // fixed order -> deterministic
            s += scr[(half * 4 + wm) * 64 + l64];
            q += scr[512 + (half * 4 + wm) * 64 + l64];
        }
        psum[blockIdx.y * OC + col0 + tid] = s;
        psq [blockIdx.y * OC + col0 + tid] = q;
    }
}

// device-side binding of the global scratch buffers
__global__ __launch_bounds__(256, 2) void k_gemm1_mma() {
    gemm_body<KIN>(g_featH, g_featL, g_w1h, g_w1l, g_h1, g_ps1, g_pq1);
}
__global__ __launch_bounds__(256, 2) void k_gemm2_mma() {
    gemm_body<OC>(g_h1H, g_h1L, g_w2h, g_w2l, g_h2, g_ps2, g_pq2);
}

// ---------------- BN finalize: reduce 512 partial blocks, fixed order ----------------
__device__ __forceinline__ void fin_body(const float* __restrict__ psum,
                                         const float* __restrict__ psq,
                                         const float* __restrict__ gamma,
                                         const float* __restrict__ beta,
                                         float* __restrict__ scale,
                                         float* __restrict__ bias) {
    const int c = threadIdx.x;
    float s = 0.f, q = 0.f;
    for (int i = 0; i < NBLK; i++) { s += psum[i * OC + c]; q += psq[i * OC + c]; }
    const float invN = 1.f / (float)ROWS;
    const float mean = s * invN;
    const float var  = q * invN - mean * mean;
    const float sc   = gamma[c] * rsqrtf(var + EPSBN);
    scale[c] = sc;
    bias[c]  = fmaf(-mean, sc, beta[c]);
}
__global__ void k_fin1(const float* __restrict__ g, const float* __restrict__ b) {
    fin_body(g_ps1, g_pq1, g, b, g_scale1, g_bias1);
}
__global__ void k_fin2(const float* __restrict__ g, const float* __restrict__ b) {
    fin_body(g_ps2, g_pq2, g, b, g_scale2, g_bias2);
}

// ---------------- BN1+ReLU -> split-bf16 GEMM2 input ----------------
__global__ void k_bnrelu1() {
    const size_t idx = ((size_t)blockIdx.x * 256 + threadIdx.x) * 4;
    const int c0 = (int)(idx & (OC - 1));
    const float4 v  = *(const float4*)(g_h1 + idx);
    const float4 sc = *(const float4*)(g_scale1 + c0);
    const float4 bi = *(const float4*)(g_bias1 + c0);
    float r[4];
    r[0] = fmaxf(fmaf(v.x, sc.x, bi.x), 0.f);
    r[1] = fmaxf(fmaf(v.y, sc.y, bi.y), 0.f);
    r[2] = fmaxf(fmaf(v.z, sc.z, bi.z), 0.f);
    r[3] = fmaxf(fmaf(v.w, sc.w, bi.w), 0.f);
    union { __nv_bfloat16 b4[4]; uint2 u; } uh, ul;
#pragma unroll
    for (int q = 0; q < 4; q++) split_bf16(r[q], uh.b4[q], ul.b4[q]);
    *(uint2*)(g_h1H + idx) = uh.u;
    *(uint2*)(g_h1L + idx) = ul.u;
}

// ---------------- BN2+ReLU + transpose to (B, 256, N) ----------------
__global__ void k_out(float* __restrict__ out) {
    __shared__ float tile[32][33];
    const int b  = blockIdx.z;
    const int n0 = blockIdx.x * 32, c0 = blockIdx.y * 32;
    const int tx = threadIdx.x, ty = threadIdx.y;
#pragma unroll
    for (int i = 0; i < 4; i++) {
        const int n = n0 + ty + i * 8, c = c0 + tx;
        const float v = g_h2[(size_t)(b * NPTS + n) * OC + c];
        tile[ty + i * 8][tx] = fmaxf(fmaf(v, g_scale2[c], g_bias2[c]), 0.f);
    }
    __syncthreads();
    float* o = out + (size_t)b * OC * NPTS;
#pragma unroll
    for (int i = 0; i < 4; i++)
        o[(size_t)(c0 + ty + i * 8) * NPTS + n0 + tx] = tile[tx][ty + i * 8];
}

// ---------------- launch (only harness pointers cross the host/device boundary) ----
extern "C" void kernel_launch(void* const* d_in, const int* in_sizes, int n_in,
                              void* d_out, int out_size) {
    const float* xyz1    = (const float*)d_in[0];
    const float* xyz2    = (const float*)d_in[1];
    const float* points1 = (const float*)d_in[2];
    const float* points2 = (const float*)d_in[3];
    const float* W1      = (const float*)d_in[4];
    const float* gamma1  = (const float*)d_in[5];
    const float* beta1   = (const float*)d_in[6];
    const float* W2      = (const float*)d_in[7];
    const float* gamma2  = (const float*)d_in[8];
    const float* beta2   = (const float*)d_in[9];
    float* out = (float*)d_out;

    k_transpose_p2<<<dim3(MPTS / 32, C2CH / 32, BB), dim3(32, 8)>>>(points2);
    k_knn<<<dim3(NPTS / 256, BB), 256>>>(xyz1, xyz2);
    k_interp<<<ROWS / 4, 128>>>();
    k_transpose_p1<<<dim3(NPTS / 32, C1CH / 32, BB), dim3(32, 8)>>>(points1);
    k_prep_w<<<(OC * KIN + 255) / 256, 256>>>(W1, W2);

    k_gemm1_mma<<<dim3(OC / 128, ROWS / 128), 256>>>();
    k_fin1<<<1, 256>>>(gamma1, beta1);
    k_bnrelu1<<<(ROWS * OC) / 1024, 256>>>();

    k_gemm2_mma<<<dim3(OC / 128, ROWS / 128), 256>>>();
    k_fin2<<<1, 256>>>(gamma2, beta2);

    k_out<<<dim3(NPTS / 32, OC / 32, BB), dim3(32, 8)>>>(out);
}